// round 12
// baseline (speedup 1.0000x reference)
#include <cuda_runtime.h>

// score[e] = sum_d h[src[e], d] * h[dst[e], d]
// h: [100000, 32] fp32 ; src/dst: int32 [E] ; out: fp32 [E]
//
// Proven-best structure (26.6us): 8 lanes per group, 4 edges per group,
// 8 independent float4 gathers (one 128B line per gathered row, MLP=8),
// 4-shuffle value-halving reduction, distributed coalesced store, block=128.
//
// This round: all gather offsets computed in 32-bit (max offset = 100000*32
// floats = 12.8MB < 2^31), eliminating IMAD.WIDE 64-bit address chains that
// showed up as ALU=29.4% in the R10 profile.

static constexpr int D = 32;
static constexpr int EDGES_PER_GROUP = 4;
static constexpr unsigned FULL = 0xFFFFFFFFu;

__device__ __forceinline__ float dot4(float4 a, float4 b) {
    return a.x * b.x + a.y * b.y + a.z * b.z + a.w * b.w;
}

__device__ __forceinline__ float red8(float p) {
    p += __shfl_xor_sync(FULL, p, 1);
    p += __shfl_xor_sync(FULL, p, 2);
    p += __shfl_xor_sync(FULL, p, 4);
    return p;
}

// 32-bit offset gather: lane i of the group reads float4 #i of row idx
__device__ __forceinline__ float4 grow(const float* __restrict__ h,
                                       unsigned idx, unsigned i) {
    unsigned off = (idx << 5) + (i << 2);   // idx*D + i*4, fits in 32 bits
    return *reinterpret_cast<const float4*>(h + off);
}

__global__ __launch_bounds__(128, 16) void edge_dot_kernel(
    const float* __restrict__ h,
    const int* __restrict__ src,
    const int* __restrict__ dst,
    float* __restrict__ out,
    int E)
{
    int gid = blockIdx.x * blockDim.x + threadIdx.x;
    int g = gid >> 3;                 // 8-lane group index
    unsigned i = (unsigned)(gid & 7); // lane within group
    long long e0 = (long long)g * EDGES_PER_GROUP;
    if (e0 >= E) return;

    if (e0 + EDGES_PER_GROUP <= E) {
        int4 s4 = *reinterpret_cast<const int4*>(src + e0);
        int4 d4 = *reinterpret_cast<const int4*>(dst + e0);

        // 8 independent gathers in flight (32-bit offset arithmetic)
        float4 a0 = grow(h, (unsigned)s4.x, i);
        float4 b0 = grow(h, (unsigned)d4.x, i);
        float4 a1 = grow(h, (unsigned)s4.y, i);
        float4 b1 = grow(h, (unsigned)d4.y, i);
        float4 a2 = grow(h, (unsigned)s4.z, i);
        float4 b2 = grow(h, (unsigned)d4.z, i);
        float4 a3 = grow(h, (unsigned)s4.w, i);
        float4 b3 = grow(h, (unsigned)d4.w, i);

        float p0 = dot4(a0, b0);
        float p1 = dot4(a1, b1);
        float p2 = dot4(a2, b2);
        float p3 = dot4(a3, b3);

        // --- value-halving reduction over the 8-lane group (4 shuffles) ---
        bool hi4 = (i & 4) != 0;
        float ua = hi4 ? p0 : p2;
        float va = __shfl_xor_sync(FULL, ua, 4);
        float ub = hi4 ? p1 : p3;
        float vb = __shfl_xor_sync(FULL, ub, 4);
        float q0 = (hi4 ? p2 : p0) + va;
        float q1 = (hi4 ? p3 : p1) + vb;

        bool hi2 = (i & 2) != 0;
        float uc = hi2 ? q0 : q1;
        float vc = __shfl_xor_sync(FULL, uc, 2);
        float r = (hi2 ? q1 : q0) + vc;

        r += __shfl_xor_sync(FULL, r, 1);

        // lane 2k holds the full sum for edge e0+k (k = i>>1)
        if ((i & 1) == 0) out[e0 + (i >> 1)] = r;
    } else {
        // remainder (E not divisible by 4)
        for (long long e = e0; e < E; ++e) {
            float4 a = grow(h, (unsigned)src[e], i);
            float4 b = grow(h, (unsigned)dst[e], i);
            float p = red8(dot4(a, b));
            if (i == 0) out[e] = p;
        }
    }
}

extern "C" void kernel_launch(void* const* d_in, const int* in_sizes, int n_in,
                              void* d_out, int out_size)
{
    const float* h   = (const float*)d_in[0];
    const int*   src = (const int*)d_in[1];
    const int*   dst = (const int*)d_in[2];
    float*       out = (float*)d_out;

    int E = in_sizes[1];
    long long groups = ((long long)E + EDGES_PER_GROUP - 1) / EDGES_PER_GROUP;
    long long total_threads = groups * 8;
    int block = 128;
    int grid = (int)((total_threads + block - 1) / block);

    edge_dot_kernel<<<grid, block>>>(h, src, dst, out, E);
}

// round 13
// speedup vs baseline: 1.0060x; 1.0060x over previous
#include <cuda_runtime.h>

// score[e] = sum_d h[src[e], d] * h[dst[e], d]
// h: [100000, 32] fp32 ; src/dst: int32 [E] ; out: fp32 [E]
//
// Best measured structure (26.6us): 8 lanes per group, 4 edges per group,
// 8 independent float4 gathers (one 128B line per gathered row, MLP=8),
// 4-shuffle value-halving reduction, distributed coalesced store,
// block=128 x 16 CTAs/SM.
//
// This round: row gathers use __ldcg (ld.global.cg, L2-only) — the h table
// has ~2% L1 hit rate (12.8MB vs 228KB), so L1 allocation of 3.2M lines is
// pure fill/evict overhead; bypassing keeps wavefronts identical but removes
// the L1 thrash. Indices/stores keep default caching (sequential streams).

static constexpr int D = 32;
static constexpr int EDGES_PER_GROUP = 4;
static constexpr unsigned FULL = 0xFFFFFFFFu;

__device__ __forceinline__ float dot4(float4 a, float4 b) {
    return a.x * b.x + a.y * b.y + a.z * b.z + a.w * b.w;
}

__device__ __forceinline__ float red8(float p) {
    p += __shfl_xor_sync(FULL, p, 1);
    p += __shfl_xor_sync(FULL, p, 2);
    p += __shfl_xor_sync(FULL, p, 4);
    return p;
}

// L2-only gather: lane i of the group reads float4 #i of row idx
__device__ __forceinline__ float4 grow(const float* __restrict__ h,
                                       int idx, int i) {
    return __ldcg(reinterpret_cast<const float4*>(h + (long long)idx * D) + i);
}

__global__ __launch_bounds__(128, 16) void edge_dot_kernel(
    const float* __restrict__ h,
    const int* __restrict__ src,
    const int* __restrict__ dst,
    float* __restrict__ out,
    int E)
{
    int gid = blockIdx.x * blockDim.x + threadIdx.x;
    int g = gid >> 3;                 // 8-lane group index
    int i = gid & 7;                  // lane within group
    long long e0 = (long long)g * EDGES_PER_GROUP;
    if (e0 >= E) return;

    if (e0 + EDGES_PER_GROUP <= E) {
        int4 s4 = *reinterpret_cast<const int4*>(src + e0);
        int4 d4 = *reinterpret_cast<const int4*>(dst + e0);

        // 8 independent L2-only gathers in flight
        float4 a0 = grow(h, s4.x, i);
        float4 b0 = grow(h, d4.x, i);
        float4 a1 = grow(h, s4.y, i);
        float4 b1 = grow(h, d4.y, i);
        float4 a2 = grow(h, s4.z, i);
        float4 b2 = grow(h, d4.z, i);
        float4 a3 = grow(h, s4.w, i);
        float4 b3 = grow(h, d4.w, i);

        float p0 = dot4(a0, b0);
        float p1 = dot4(a1, b1);
        float p2 = dot4(a2, b2);
        float p3 = dot4(a3, b3);

        // --- value-halving reduction over the 8-lane group (4 shuffles) ---
        bool hi4 = (i & 4) != 0;
        float ua = hi4 ? p0 : p2;
        float va = __shfl_xor_sync(FULL, ua, 4);
        float ub = hi4 ? p1 : p3;
        float vb = __shfl_xor_sync(FULL, ub, 4);
        float q0 = (hi4 ? p2 : p0) + va;
        float q1 = (hi4 ? p3 : p1) + vb;

        bool hi2 = (i & 2) != 0;
        float uc = hi2 ? q0 : q1;
        float vc = __shfl_xor_sync(FULL, uc, 2);
        float r = (hi2 ? q1 : q0) + vc;

        r += __shfl_xor_sync(FULL, r, 1);

        // lane 2k holds the full sum for edge e0+k (k = i>>1)
        if ((i & 1) == 0) out[e0 + (i >> 1)] = r;
    } else {
        // remainder (E not divisible by 4)
        for (long long e = e0; e < E; ++e) {
            float4 a = grow(h, src[e], i);
            float4 b = grow(h, dst[e], i);
            float p = red8(dot4(a, b));
            if (i == 0) out[e] = p;
        }
    }
}

extern "C" void kernel_launch(void* const* d_in, const int* in_sizes, int n_in,
                              void* d_out, int out_size)
{
    const float* h   = (const float*)d_in[0];
    const int*   src = (const int*)d_in[1];
    const int*   dst = (const int*)d_in[2];
    float*       out = (float*)d_out;

    int E = in_sizes[1];
    long long groups = ((long long)E + EDGES_PER_GROUP - 1) / EDGES_PER_GROUP;
    long long total_threads = groups * 8;
    int block = 128;
    int grid = (int)((total_threads + block - 1) / block);

    edge_dot_kernel<<<grid, block>>>(h, src, dst, out, E);
}